// round 1
// baseline (speedup 1.0000x reference)
#include <cuda_runtime.h>
#include <cuda_bf16.h>

// ---------------------------------------------------------------------------
// ViT encoder block, fp32 SIMT baseline.
// x:[32,512,768]  ->  out:[32,512,768]
// ---------------------------------------------------------------------------

#define NTOK   16384      // 32*512
#define EMB    768
#define FFND   3072
#define HEADS  12
#define DK     64
#define SEQ    512
#define BATCH  32

// Scratch (static device allocations are the sanctioned way to get scratch).
__device__ __align__(128) float g_q  [NTOK * EMB];
__device__ __align__(128) float g_k  [NTOK * EMB];
__device__ __align__(128) float g_v  [NTOK * EMB];
__device__ __align__(128) float g_ctx[NTOK * EMB];
__device__ __align__(128) float g_tmp[NTOK * EMB];
__device__ __align__(128) float g_x1 [NTOK * EMB];
__device__ __align__(128) float g_ffn[NTOK * FFND];

// ---------------------------------------------------------------------------
// GEMM: C[M,N] = A[M,K] * B[K,N]  (+bias) (+relu). All row-major.
// 128x128 tile, BK=8, 256 threads, 8x8 per-thread microtile.
// M,N,K all multiples of tile dims for every call site (no edge handling).
// EPI: 0=none, 1=+bias, 2=+bias+relu
// ---------------------------------------------------------------------------
template <int EPI>
__global__ __launch_bounds__(256) void gemm_kernel(
    const float* __restrict__ A, const float* __restrict__ B,
    const float* __restrict__ bias, float* __restrict__ C,
    int M, int N, int K)
{
    __shared__ float As[8][128];   // As[k][m]
    __shared__ float Bs[8][128];   // Bs[k][n]

    const int tid = threadIdx.x;
    const int bm  = blockIdx.y * 128;
    const int bn  = blockIdx.x * 128;

    const int tx = tid & 15;   // n direction (16)
    const int ty = tid >> 4;   // m direction (16)

    float acc[8][8];
#pragma unroll
    for (int i = 0; i < 8; i++)
#pragma unroll
        for (int j = 0; j < 8; j++) acc[i][j] = 0.f;

    // A tile loader: thread -> (row 0..127, col {0,4})
    const int a_r = tid >> 1;
    const int a_c = (tid & 1) * 4;
    // B tile loader: thread -> (row 0..7, col 0..124 step 4)
    const int b_r = tid >> 5;
    const int b_c = (tid & 31) * 4;

    const float* Aptr = A + (long)(bm + a_r) * K + a_c;
    const float* Bptr = B + (long)b_r * N + bn + b_c;

    for (int k0 = 0; k0 < K; k0 += 8) {
        float4 av = *(const float4*)Aptr;
        float4 bv = *(const float4*)Bptr;
        As[a_c + 0][a_r] = av.x;
        As[a_c + 1][a_r] = av.y;
        As[a_c + 2][a_r] = av.z;
        As[a_c + 3][a_r] = av.w;
        *(float4*)&Bs[b_r][b_c] = bv;
        __syncthreads();

#pragma unroll
        for (int kk = 0; kk < 8; kk++) {
            float4 a0 = *(float4*)&As[kk][ty * 8];
            float4 a1 = *(float4*)&As[kk][ty * 8 + 4];
            float4 b0 = *(float4*)&Bs[kk][tx * 8];
            float4 b1 = *(float4*)&Bs[kk][tx * 8 + 4];
            float ar[8] = {a0.x, a0.y, a0.z, a0.w, a1.x, a1.y, a1.z, a1.w};
            float br[8] = {b0.x, b0.y, b0.z, b0.w, b1.x, b1.y, b1.z, b1.w};
#pragma unroll
            for (int i = 0; i < 8; i++)
#pragma unroll
                for (int j = 0; j < 8; j++)
                    acc[i][j] += ar[i] * br[j];
        }
        __syncthreads();
        Aptr += 8;
        Bptr += (long)8 * N;
    }

    // epilogue
    float4 bia0 = make_float4(0.f, 0.f, 0.f, 0.f), bia1 = bia0;
    if (EPI >= 1) {
        bia0 = *(const float4*)&bias[bn + tx * 8];
        bia1 = *(const float4*)&bias[bn + tx * 8 + 4];
    }
#pragma unroll
    for (int i = 0; i < 8; i++) {
        const long row = bm + ty * 8 + i;
        float4 o0 = make_float4(acc[i][0], acc[i][1], acc[i][2], acc[i][3]);
        float4 o1 = make_float4(acc[i][4], acc[i][5], acc[i][6], acc[i][7]);
        if (EPI >= 1) {
            o0.x += bia0.x; o0.y += bia0.y; o0.z += bia0.z; o0.w += bia0.w;
            o1.x += bia1.x; o1.y += bia1.y; o1.z += bia1.z; o1.w += bia1.w;
        }
        if (EPI == 2) {
            o0.x = fmaxf(o0.x, 0.f); o0.y = fmaxf(o0.y, 0.f);
            o0.z = fmaxf(o0.z, 0.f); o0.w = fmaxf(o0.w, 0.f);
            o1.x = fmaxf(o1.x, 0.f); o1.y = fmaxf(o1.y, 0.f);
            o1.z = fmaxf(o1.z, 0.f); o1.w = fmaxf(o1.w, 0.f);
        }
        *(float4*)&C[row * N + bn + tx * 8]     = o0;
        *(float4*)&C[row * N + bn + tx * 8 + 4] = o1;
    }
}

// ---------------------------------------------------------------------------
// Attention: per block = one (b, h, 32 q rows).
// Q/K/V stored token-major [NTOK, EMB]; head h occupies cols [h*64, h*64+64).
// Full 32x512 score block kept in smem; softmax in-place; ctx = P @ V.
// dyn smem: sQ 32*64 | sK 64*64 | sKt 64*68 | sS 32*512  = 107,520 B
// ---------------------------------------------------------------------------
__global__ __launch_bounds__(256) void attn_kernel(
    const float* __restrict__ Q, const float* __restrict__ K,
    const float* __restrict__ V, float* __restrict__ O)
{
    extern __shared__ float sm[];
    float* sQ  = sm;                 // 2048
    float* sK  = sQ + 2048;          // 4096
    float* sKt = sK + 4096;          // 64*68 = 4352
    float* sS  = sKt + 4352;         // 16384

    const int qt  = blockIdx.x;      // 0..15
    const int h   = blockIdx.y;      // 0..11
    const int b   = blockIdx.z;      // 0..31
    const int tid = threadIdx.x;

    const long base = (long)b * SEQ * EMB + h * DK;

    // Load Q tile (32 x 64), float4 coalesced.
    for (int i = tid; i < 512; i += 256) {
        int r = i >> 4, c = (i & 15) * 4;
        *(float4*)&sQ[r * 64 + c] =
            *(const float4*)&Q[base + (long)(qt * 32 + r) * EMB + c];
    }

    const int gq  = tid >> 4;        // 0..15 -> q pair
    const int gk  = tid & 15;        // 0..15 -> 4-wide col group
    const int qi0 = gq * 2;
    const int kj0 = gk * 4;

    // ---- scores: S = (Q K^T) * 1/sqrt(DK) ----
    for (int kt = 0; kt < 8; kt++) {
        __syncthreads();
        for (int i = tid; i < 1024; i += 256) {
            int r = i >> 4, c = (i & 15) * 4;
            *(float4*)&sK[r * 64 + c] =
                *(const float4*)&K[base + (long)(kt * 64 + r) * EMB + c];
        }
        __syncthreads();
        // transpose into sKt[d][r] (stride 68)
        for (int i = tid; i < 4096; i += 256) {
            int d = i & 63, r = i >> 6;
            sKt[d * 68 + r] = sK[r * 64 + d];
        }
        __syncthreads();

        float acc[2][4] = {{0.f,0.f,0.f,0.f},{0.f,0.f,0.f,0.f}};
#pragma unroll 8
        for (int d = 0; d < 64; d++) {
            float q0 = sQ[qi0 * 64 + d];
            float q1 = sQ[qi0 * 64 + 64 + d];
            float4 kv = *(float4*)&sKt[d * 68 + kj0];
            acc[0][0] += q0 * kv.x; acc[0][1] += q0 * kv.y;
            acc[0][2] += q0 * kv.z; acc[0][3] += q0 * kv.w;
            acc[1][0] += q1 * kv.x; acc[1][1] += q1 * kv.y;
            acc[1][2] += q1 * kv.z; acc[1][3] += q1 * kv.w;
        }
#pragma unroll
        for (int i = 0; i < 2; i++)
#pragma unroll
            for (int j = 0; j < 4; j++)
                sS[(qi0 + i) * 512 + kt * 64 + kj0 + j] = acc[i][j] * 0.125f;
    }
    __syncthreads();

    // ---- softmax: one warp per 4 rows ----
    {
        const int wid = tid >> 5, lane = tid & 31;
        for (int r = wid * 4; r < wid * 4 + 4; r++) {
            float* srow = sS + r * 512;
            float m = -1e30f;
            for (int c = lane; c < 512; c += 32) m = fmaxf(m, srow[c]);
#pragma unroll
            for (int o = 16; o > 0; o >>= 1)
                m = fmaxf(m, __shfl_xor_sync(0xffffffffu, m, o));
            float s = 0.f;
            for (int c = lane; c < 512; c += 32) {
                float e = __expf(srow[c] - m);
                srow[c] = e;
                s += e;
            }
#pragma unroll
            for (int o = 16; o > 0; o >>= 1)
                s += __shfl_xor_sync(0xffffffffu, s, o);
            float inv = 1.0f / s;
            for (int c = lane; c < 512; c += 32) srow[c] *= inv;
        }
    }

    // ---- ctx = P @ V ----
    const int d0 = gk * 4;
    float o_[2][4] = {{0.f,0.f,0.f,0.f},{0.f,0.f,0.f,0.f}};
    for (int kt = 0; kt < 8; kt++) {
        __syncthreads();
        for (int i = tid; i < 1024; i += 256) {
            int r = i >> 4, c = (i & 15) * 4;
            *(float4*)&sK[r * 64 + c] =
                *(const float4*)&V[base + (long)(kt * 64 + r) * EMB + c];
        }
        __syncthreads();
#pragma unroll 4
        for (int k = 0; k < 64; k++) {
            float s0 = sS[qi0 * 512 + kt * 64 + k];
            float s1 = sS[qi0 * 512 + 512 + kt * 64 + k];
            float4 vv = *(float4*)&sK[k * 64 + d0];
            o_[0][0] += s0 * vv.x; o_[0][1] += s0 * vv.y;
            o_[0][2] += s0 * vv.z; o_[0][3] += s0 * vv.w;
            o_[1][0] += s1 * vv.x; o_[1][1] += s1 * vv.y;
            o_[1][2] += s1 * vv.z; o_[1][3] += s1 * vv.w;
        }
    }

#pragma unroll
    for (int i = 0; i < 2; i++) {
        float4 ov = make_float4(o_[i][0], o_[i][1], o_[i][2], o_[i][3]);
        *(float4*)&O[base + (long)(qt * 32 + qi0 + i) * EMB + d0] = ov;
    }
}

// ---------------------------------------------------------------------------
// Fused residual + LayerNorm: out = LN(x + r) * gamma + beta
// One 256-thread block per token row (768 = 3*256).
// ---------------------------------------------------------------------------
__global__ __launch_bounds__(256) void add_ln_kernel(
    const float* __restrict__ x, const float* __restrict__ r,
    const float* __restrict__ gamma, const float* __restrict__ beta,
    float* __restrict__ out)
{
    const int row = blockIdx.x;
    const int tid = threadIdx.x;
    const float* xr = x + (long)row * EMB;
    const float* rr = r + (long)row * EMB;

    float v[3];
    float s = 0.f;
#pragma unroll
    for (int i = 0; i < 3; i++) {
        int c = tid + i * 256;
        float t = xr[c] + rr[c];
        v[i] = t;
        s += t;
    }

    __shared__ float red[8];
    const int wid = tid >> 5, lane = tid & 31;
#pragma unroll
    for (int o = 16; o > 0; o >>= 1) s += __shfl_xor_sync(0xffffffffu, s, o);
    if (lane == 0) red[wid] = s;
    __syncthreads();
    if (tid == 0) {
        float t = 0.f;
#pragma unroll
        for (int i = 0; i < 8; i++) t += red[i];
        red[0] = t;
    }
    __syncthreads();
    const float mean = red[0] * (1.0f / 768.0f);

    float s2 = 0.f;
#pragma unroll
    for (int i = 0; i < 3; i++) {
        float d = v[i] - mean;
        s2 += d * d;
    }
#pragma unroll
    for (int o = 16; o > 0; o >>= 1) s2 += __shfl_xor_sync(0xffffffffu, s2, o);
    __syncthreads();
    if (lane == 0) red[wid] = s2;
    __syncthreads();
    if (tid == 0) {
        float t = 0.f;
#pragma unroll
        for (int i = 0; i < 8; i++) t += red[i];
        red[0] = t;
    }
    __syncthreads();
    const float var  = red[0] * (1.0f / 768.0f);
    const float rstd = rsqrtf(var + 1e-5f);

#pragma unroll
    for (int i = 0; i < 3; i++) {
        int c = tid + i * 256;
        out[(long)row * EMB + c] = (v[i] - mean) * rstd * gamma[c] + beta[c];
    }
}

// ---------------------------------------------------------------------------
// Launch
// ---------------------------------------------------------------------------
extern "C" void kernel_launch(void* const* d_in, const int* in_sizes, int n_in,
                              void* d_out, int out_size)
{
    (void)in_sizes; (void)n_in; (void)out_size;

    const float* x   = (const float*)d_in[0];
    const float* Wq  = (const float*)d_in[1];
    const float* Wk  = (const float*)d_in[2];
    const float* Wv  = (const float*)d_in[3];
    const float* Wo  = (const float*)d_in[4];
    const float* W1  = (const float*)d_in[5];
    const float* b1  = (const float*)d_in[6];
    const float* W2  = (const float*)d_in[7];
    const float* b2  = (const float*)d_in[8];
    const float* g1  = (const float*)d_in[9];
    const float* be1 = (const float*)d_in[10];
    const float* g2  = (const float*)d_in[11];
    const float* be2 = (const float*)d_in[12];
    float* out = (float*)d_out;

    float *q, *k, *v, *ctx, *tmp, *x1, *ffn;
    cudaGetSymbolAddress((void**)&q,   g_q);
    cudaGetSymbolAddress((void**)&k,   g_k);
    cudaGetSymbolAddress((void**)&v,   g_v);
    cudaGetSymbolAddress((void**)&ctx, g_ctx);
    cudaGetSymbolAddress((void**)&tmp, g_tmp);
    cudaGetSymbolAddress((void**)&x1,  g_x1);
    cudaGetSymbolAddress((void**)&ffn, g_ffn);

    const int ATTN_SMEM = (2048 + 4096 + 64 * 68 + 16384) * 4;  // 107,520 B
    cudaFuncSetAttribute(attn_kernel,
                         cudaFuncAttributeMaxDynamicSharedMemorySize, ATTN_SMEM);

    dim3 blk(256);
    dim3 gE(EMB / 128,  NTOK / 128);   // (6, 128)
    dim3 gF(FFND / 128, NTOK / 128);   // (24, 128)

    // QKV projections
    gemm_kernel<0><<<gE, blk>>>(x, Wq, nullptr, q, NTOK, EMB, EMB);
    gemm_kernel<0><<<gE, blk>>>(x, Wk, nullptr, k, NTOK, EMB, EMB);
    gemm_kernel<0><<<gE, blk>>>(x, Wv, nullptr, v, NTOK, EMB, EMB);

    // Attention
    attn_kernel<<<dim3(SEQ / 32, HEADS, BATCH), blk, ATTN_SMEM>>>(q, k, v, ctx);

    // Output projection
    gemm_kernel<0><<<gE, blk>>>(ctx, Wo, nullptr, tmp, NTOK, EMB, EMB);

    // Residual + LN1
    add_ln_kernel<<<NTOK, blk>>>(x, tmp, g1, be1, x1);

    // FFN
    gemm_kernel<2><<<gF, blk>>>(x1, W1, b1, ffn, NTOK, FFND, EMB);
    gemm_kernel<1><<<gE, blk>>>(ffn, W2, b2, tmp, NTOK, EMB, FFND);

    // Residual + LN2
    add_ln_kernel<<<NTOK, blk>>>(x1, tmp, g2, be2, out);
}

// round 2
// speedup vs baseline: 1.9957x; 1.9957x over previous
#include <cuda_runtime.h>
#include <cuda_bf16.h>
#include <cstdint>

// ---------------------------------------------------------------------------
// ViT encoder block. GEMMs on tensor cores via bf16 2-term split (3 MMAs):
//   C = Ah*Bh + Ah*Bl + Al*Bh   (error ~2^-16, well under 1e-3 budget)
// Attention + LayerNorm stay fp32 SIMT.
// ---------------------------------------------------------------------------

#define NTOK   16384
#define EMB    768
#define FFND   3072
#define HEADS  12
#define DK     64
#define SEQ    512
#define BATCH  32

// ----- fp32 scratch -----
__device__ __align__(128) float g_q  [NTOK * EMB];
__device__ __align__(128) float g_k  [NTOK * EMB];
__device__ __align__(128) float g_v  [NTOK * EMB];
__device__ __align__(128) float g_tmp[NTOK * EMB];
__device__ __align__(128) float g_x1 [NTOK * EMB];

// ----- bf16 split scratch -----
__device__ __align__(128) __nv_bfloat16 g_ah[NTOK * EMB];   // activation hi (x, then x1)
__device__ __align__(128) __nv_bfloat16 g_al[NTOK * EMB];
__device__ __align__(128) __nv_bfloat16 g_ch[NTOK * EMB];   // ctx hi/lo (attn output)
__device__ __align__(128) __nv_bfloat16 g_cl[NTOK * EMB];
__device__ __align__(128) __nv_bfloat16 g_fh[NTOK * FFND];  // relu(ffn) hi/lo
__device__ __align__(128) __nv_bfloat16 g_fl[NTOK * FFND];
#define WTOT 7077888
__device__ __align__(128) __nv_bfloat16 g_wh[WTOT];
__device__ __align__(128) __nv_bfloat16 g_wl[WTOT];

// ---------------------------------------------------------------------------
// split: fp32 -> bf16 hi + bf16 lo
// ---------------------------------------------------------------------------
__global__ __launch_bounds__(256) void split_kernel(
    const float* __restrict__ in, __nv_bfloat16* __restrict__ h,
    __nv_bfloat16* __restrict__ l, int n)
{
    int i = (blockIdx.x * 256 + threadIdx.x) * 4;
    if (i >= n) return;
    float4 v = *(const float4*)(in + i);
    __nv_bfloat16 h0 = __float2bfloat16(v.x);
    __nv_bfloat16 h1 = __float2bfloat16(v.y);
    __nv_bfloat16 h2 = __float2bfloat16(v.z);
    __nv_bfloat16 h3 = __float2bfloat16(v.w);
    __nv_bfloat16 l0 = __float2bfloat16(v.x - __bfloat162float(h0));
    __nv_bfloat16 l1 = __float2bfloat16(v.y - __bfloat162float(h1));
    __nv_bfloat16 l2 = __float2bfloat16(v.z - __bfloat162float(h2));
    __nv_bfloat16 l3 = __float2bfloat16(v.w - __bfloat162float(h3));
    __nv_bfloat162 a; a.x = h0; a.y = h1;
    __nv_bfloat162 b; b.x = h2; b.y = h3;
    __nv_bfloat162 c; c.x = l0; c.y = l1;
    __nv_bfloat162 d; d.x = l2; d.y = l3;
    *reinterpret_cast<__nv_bfloat162*>(h + i)     = a;
    *reinterpret_cast<__nv_bfloat162*>(h + i + 2) = b;
    *reinterpret_cast<__nv_bfloat162*>(l + i)     = c;
    *reinterpret_cast<__nv_bfloat162*>(l + i + 2) = d;
}

// ---------------------------------------------------------------------------
// Tensor-core GEMM: C[M,N] = A[M,K] @ B[K,N], A/B given as bf16 hi/lo pairs.
// 128x128 block tile, BK=16, 256 threads (4x2 warps, 32x64 warp tile).
// EPI: 0 = plain fp32 C;  1 = +bias fp32 C;  3 = +bias +relu -> bf16 split out
// ---------------------------------------------------------------------------
__device__ __forceinline__ void ldsm4(uint32_t* r, const void* p) {
    uint32_t a = (uint32_t)__cvta_generic_to_shared(p);
    asm volatile("ldmatrix.sync.aligned.m8n8.x4.shared.b16 {%0,%1,%2,%3}, [%4];"
                 : "=r"(r[0]), "=r"(r[1]), "=r"(r[2]), "=r"(r[3]) : "r"(a));
}
__device__ __forceinline__ void ldsm4t(uint32_t* r, const void* p) {
    uint32_t a = (uint32_t)__cvta_generic_to_shared(p);
    asm volatile("ldmatrix.sync.aligned.m8n8.x4.trans.shared.b16 {%0,%1,%2,%3}, [%4];"
                 : "=r"(r[0]), "=r"(r[1]), "=r"(r[2]), "=r"(r[3]) : "r"(a));
}
__device__ __forceinline__ void mma16816(float* c, const uint32_t* a, const uint32_t* b) {
    asm volatile("mma.sync.aligned.m16n8k16.row.col.f32.bf16.bf16.f32 "
                 "{%0,%1,%2,%3}, {%4,%5,%6,%7}, {%8,%9}, {%0,%1,%2,%3};"
                 : "+f"(c[0]), "+f"(c[1]), "+f"(c[2]), "+f"(c[3])
                 : "r"(a[0]), "r"(a[1]), "r"(a[2]), "r"(a[3]), "r"(b[0]), "r"(b[1]));
}

#define ASTR 24    // A smem row stride (elems), conflict-free ldmatrix
#define BSTR 136   // B smem row stride

template <int EPI>
__global__ __launch_bounds__(256) void tgemm(
    const __nv_bfloat16* __restrict__ Ah, const __nv_bfloat16* __restrict__ Al,
    const __nv_bfloat16* __restrict__ Bh, const __nv_bfloat16* __restrict__ Bl,
    const float* __restrict__ bias,
    float* __restrict__ C,
    __nv_bfloat16* __restrict__ Ch, __nv_bfloat16* __restrict__ Cl,
    int M, int N, int K)
{
    __shared__ __align__(16) __nv_bfloat16 sAh[2][128 * ASTR];
    __shared__ __align__(16) __nv_bfloat16 sAl[2][128 * ASTR];
    __shared__ __align__(16) __nv_bfloat16 sBh[2][16 * BSTR];
    __shared__ __align__(16) __nv_bfloat16 sBl[2][16 * BSTR];

    const int tid  = threadIdx.x;
    const int lane = tid & 31;
    const int w    = tid >> 5;
    const int wm   = w & 3;    // 0..3  -> rows wm*32
    const int wn   = w >> 2;   // 0..1  -> cols wn*64
    const int bm   = blockIdx.y * 128;
    const int bn   = blockIdx.x * 128;

    // global tile loader indices
    const int ar  = tid >> 1;          // 0..127
    const int acg = (tid & 1) * 8;     // 0 or 8
    const int br  = tid >> 4;          // 0..15
    const int bc  = (tid & 15) * 8;    // 0..120

    const __nv_bfloat16* gAh = Ah + (size_t)(bm + ar) * K + acg;
    const __nv_bfloat16* gAl = Al + (size_t)(bm + ar) * K + acg;
    const __nv_bfloat16* gBh = Bh + (size_t)br * N + bn + bc;
    const __nv_bfloat16* gBl = Bl + (size_t)br * N + bn + bc;

    // ldmatrix source offsets (within buffer)
    int a_off[2];
#pragma unroll
    for (int mi = 0; mi < 2; mi++) {
        int row = wm * 32 + mi * 16 + (lane & 7) + ((lane >> 3) & 1) * 8;
        int col = (lane >> 4) * 8;
        a_off[mi] = row * ASTR + col;
    }
    int b_off[4];
    {
        int krow = ((lane >> 3) & 1) * 8 + (lane & 7);
#pragma unroll
        for (int p = 0; p < 4; p++) {
            int col = wn * 64 + (p * 2 + (lane >> 4)) * 8;
            b_off[p] = krow * BSTR + col;
        }
    }

    float c[2][8][4];
#pragma unroll
    for (int mi = 0; mi < 2; mi++)
#pragma unroll
        for (int ni = 0; ni < 8; ni++)
#pragma unroll
            for (int e = 0; e < 4; e++) c[mi][ni][e] = 0.f;

    // prologue: tile 0 -> buf 0
    {
        uint4 vah = *(const uint4*)gAh;
        uint4 val_ = *(const uint4*)gAl;
        uint4 vbh = *(const uint4*)gBh;
        uint4 vbl = *(const uint4*)gBl;
        *(uint4*)&sAh[0][ar * ASTR + acg] = vah;
        *(uint4*)&sAl[0][ar * ASTR + acg] = val_;
        *(uint4*)&sBh[0][br * BSTR + bc]  = vbh;
        *(uint4*)&sBl[0][br * BSTR + bc]  = vbl;
    }
    __syncthreads();

    const int nk = K >> 4;
    uint4 pah, pal, pbh, pbl;
    for (int kt = 0; kt < nk; kt++) {
        const int buf = kt & 1;
        if (kt + 1 < nk) {
            int k0 = (kt + 1) * 16;
            pah = *(const uint4*)(gAh + k0);
            pal = *(const uint4*)(gAl + k0);
            pbh = *(const uint4*)(gBh + (size_t)k0 * N);
            pbl = *(const uint4*)(gBl + (size_t)k0 * N);
        }

        uint32_t fah[2][4], fal[2][4], fbh[8][2], fbl[8][2];
#pragma unroll
        for (int mi = 0; mi < 2; mi++) {
            ldsm4(fah[mi], &sAh[buf][a_off[mi]]);
            ldsm4(fal[mi], &sAl[buf][a_off[mi]]);
        }
#pragma unroll
        for (int p = 0; p < 4; p++) {
            uint32_t r[4];
            ldsm4t(r, &sBh[buf][b_off[p]]);
            fbh[p * 2][0] = r[0]; fbh[p * 2][1] = r[1];
            fbh[p * 2 + 1][0] = r[2]; fbh[p * 2 + 1][1] = r[3];
            ldsm4t(r, &sBl[buf][b_off[p]]);
            fbl[p * 2][0] = r[0]; fbl[p * 2][1] = r[1];
            fbl[p * 2 + 1][0] = r[2]; fbl[p * 2 + 1][1] = r[3];
        }

        // hh, then hl, then lh: RAW chains spaced 16 MMAs apart
#pragma unroll
        for (int mi = 0; mi < 2; mi++)
#pragma unroll
            for (int ni = 0; ni < 8; ni++) mma16816(c[mi][ni], fah[mi], fbh[ni]);
#pragma unroll
        for (int mi = 0; mi < 2; mi++)
#pragma unroll
            for (int ni = 0; ni < 8; ni++) mma16816(c[mi][ni], fah[mi], fbl[ni]);
#pragma unroll
        for (int mi = 0; mi < 2; mi++)
#pragma unroll
            for (int ni = 0; ni < 8; ni++) mma16816(c[mi][ni], fal[mi], fbh[ni]);

        if (kt + 1 < nk) {
            __syncthreads();
            const int nb = buf ^ 1;
            *(uint4*)&sAh[nb][ar * ASTR + acg] = pah;
            *(uint4*)&sAl[nb][ar * ASTR + acg] = pal;
            *(uint4*)&sBh[nb][br * BSTR + bc]  = pbh;
            *(uint4*)&sBl[nb][br * BSTR + bc]  = pbl;
            __syncthreads();
        }
    }

    // epilogue
    const int er = lane >> 2;
    const int ec = (lane & 3) * 2;
#pragma unroll
    for (int mi = 0; mi < 2; mi++) {
#pragma unroll
        for (int ni = 0; ni < 8; ni++) {
            int r0 = bm + wm * 32 + mi * 16 + er;
            int cc = bn + wn * 64 + ni * 8 + ec;
            float v0 = c[mi][ni][0], v1 = c[mi][ni][1];
            float v2 = c[mi][ni][2], v3 = c[mi][ni][3];
            if (EPI >= 1) {
                float bi0 = bias[cc], bi1 = bias[cc + 1];
                v0 += bi0; v1 += bi1; v2 += bi0; v3 += bi1;
            }
            if (EPI == 3) {
                v0 = fmaxf(v0, 0.f); v1 = fmaxf(v1, 0.f);
                v2 = fmaxf(v2, 0.f); v3 = fmaxf(v3, 0.f);
                __nv_bfloat16 h0 = __float2bfloat16(v0);
                __nv_bfloat16 h1 = __float2bfloat16(v1);
                __nv_bfloat16 h2 = __float2bfloat16(v2);
                __nv_bfloat16 h3 = __float2bfloat16(v3);
                __nv_bfloat162 hp0; hp0.x = h0; hp0.y = h1;
                __nv_bfloat162 hp1; hp1.x = h2; hp1.y = h3;
                __nv_bfloat162 lp0;
                lp0.x = __float2bfloat16(v0 - __bfloat162float(h0));
                lp0.y = __float2bfloat16(v1 - __bfloat162float(h1));
                __nv_bfloat162 lp1;
                lp1.x = __float2bfloat16(v2 - __bfloat162float(h2));
                lp1.y = __float2bfloat16(v3 - __bfloat162float(h3));
                *reinterpret_cast<__nv_bfloat162*>(&Ch[(size_t)r0 * N + cc])       = hp0;
                *reinterpret_cast<__nv_bfloat162*>(&Cl[(size_t)r0 * N + cc])       = lp0;
                *reinterpret_cast<__nv_bfloat162*>(&Ch[(size_t)(r0 + 8) * N + cc]) = hp1;
                *reinterpret_cast<__nv_bfloat162*>(&Cl[(size_t)(r0 + 8) * N + cc]) = lp1;
            } else {
                *(float2*)&C[(size_t)r0 * N + cc]       = make_float2(v0, v1);
                *(float2*)&C[(size_t)(r0 + 8) * N + cc] = make_float2(v2, v3);
            }
        }
    }
}

// ---------------------------------------------------------------------------
// Attention (fp32 SIMT), outputs ctx directly as bf16 hi/lo split.
// ---------------------------------------------------------------------------
__global__ __launch_bounds__(256) void attn_kernel(
    const float* __restrict__ Q, const float* __restrict__ K,
    const float* __restrict__ V,
    __nv_bfloat16* __restrict__ Oh, __nv_bfloat16* __restrict__ Ol)
{
    extern __shared__ float sm[];
    float* sQ  = sm;
    float* sK  = sQ + 2048;
    float* sKt = sK + 4096;
    float* sS  = sKt + 4352;

    const int qt  = blockIdx.x;
    const int h   = blockIdx.y;
    const int b   = blockIdx.z;
    const int tid = threadIdx.x;
    const size_t base = (size_t)b * SEQ * EMB + h * DK;

    for (int i = tid; i < 512; i += 256) {
        int r = i >> 4, cx = (i & 15) * 4;
        *(float4*)&sQ[r * 64 + cx] =
            *(const float4*)&Q[base + (size_t)(qt * 32 + r) * EMB + cx];
    }

    const int gq  = tid >> 4;
    const int gk  = tid & 15;
    const int qi0 = gq * 2;
    const int kj0 = gk * 4;

    for (int kt = 0; kt < 8; kt++) {
        __syncthreads();
        for (int i = tid; i < 1024; i += 256) {
            int r = i >> 4, cx = (i & 15) * 4;
            *(float4*)&sK[r * 64 + cx] =
                *(const float4*)&K[base + (size_t)(kt * 64 + r) * EMB + cx];
        }
        __syncthreads();
        for (int i = tid; i < 4096; i += 256) {
            int d = i & 63, r = i >> 6;
            sKt[d * 68 + r] = sK[r * 64 + d];
        }
        __syncthreads();

        float acc[2][4] = {{0.f,0.f,0.f,0.f},{0.f,0.f,0.f,0.f}};
#pragma unroll 8
        for (int d = 0; d < 64; d++) {
            float q0 = sQ[qi0 * 64 + d];
            float q1 = sQ[qi0 * 64 + 64 + d];
            float4 kv = *(float4*)&sKt[d * 68 + kj0];
            acc[0][0] += q0 * kv.x; acc[0][1] += q0 * kv.y;
            acc[0][2] += q0 * kv.z; acc[0][3] += q0 * kv.w;
            acc[1][0] += q1 * kv.x; acc[1][1] += q1 * kv.y;
            acc[1][2] += q1 * kv.z; acc[1][3] += q1 * kv.w;
        }
#pragma unroll
        for (int i = 0; i < 2; i++)
#pragma unroll
            for (int j = 0; j < 4; j++)
                sS[(qi0 + i) * 512 + kt * 64 + kj0 + j] = acc[i][j] * 0.125f;
    }
    __syncthreads();

    {
        const int wid = tid >> 5, lanei = tid & 31;
        for (int r = wid * 4; r < wid * 4 + 4; r++) {
            float* srow = sS + r * 512;
            float m = -1e30f;
            for (int cx = lanei; cx < 512; cx += 32) m = fmaxf(m, srow[cx]);
#pragma unroll
            for (int o = 16; o > 0; o >>= 1)
                m = fmaxf(m, __shfl_xor_sync(0xffffffffu, m, o));
            float s = 0.f;
            for (int cx = lanei; cx < 512; cx += 32) {
                float e = __expf(srow[cx] - m);
                srow[cx] = e;
                s += e;
            }
#pragma unroll
            for (int o = 16; o > 0; o >>= 1)
                s += __shfl_xor_sync(0xffffffffu, s, o);
            float inv = 1.0f / s;
            for (int cx = lanei; cx < 512; cx += 32) srow[cx] *= inv;
        }
    }

    const int d0 = gk * 4;
    float o_[2][4] = {{0.f,0.f,0.f,0.f},{0.f,0.f,0.f,0.f}};
    for (int kt = 0; kt < 8; kt++) {
        __syncthreads();
        for (int i = tid; i < 1024; i += 256) {
            int r = i >> 4, cx = (i & 15) * 4;
            *(float4*)&sK[r * 64 + cx] =
                *(const float4*)&V[base + (size_t)(kt * 64 + r) * EMB + cx];
        }
        __syncthreads();
#pragma unroll 4
        for (int k = 0; k < 64; k++) {
            float s0 = sS[qi0 * 512 + kt * 64 + k];
            float s1 = sS[qi0 * 512 + 512 + kt * 64 + k];
            float4 vv = *(float4*)&sK[k * 64 + d0];
            o_[0][0] += s0 * vv.x; o_[0][1] += s0 * vv.y;
            o_[0][2] += s0 * vv.z; o_[0][3] += s0 * vv.w;
            o_[1][0] += s1 * vv.x; o_[1][1] += s1 * vv.y;
            o_[1][2] += s1 * vv.z; o_[1][3] += s1 * vv.w;
        }
    }

#pragma unroll
    for (int i = 0; i < 2; i++) {
        size_t idx = base + (size_t)(qt * 32 + qi0 + i) * EMB + d0;
        __nv_bfloat16 h0 = __float2bfloat16(o_[i][0]);
        __nv_bfloat16 h1 = __float2bfloat16(o_[i][1]);
        __nv_bfloat16 h2 = __float2bfloat16(o_[i][2]);
        __nv_bfloat16 h3 = __float2bfloat16(o_[i][3]);
        __nv_bfloat162 hp0; hp0.x = h0; hp0.y = h1;
        __nv_bfloat162 hp1; hp1.x = h2; hp1.y = h3;
        __nv_bfloat162 lp0;
        lp0.x = __float2bfloat16(o_[i][0] - __bfloat162float(h0));
        lp0.y = __float2bfloat16(o_[i][1] - __bfloat162float(h1));
        __nv_bfloat162 lp1;
        lp1.x = __float2bfloat16(o_[i][2] - __bfloat162float(h2));
        lp1.y = __float2bfloat16(o_[i][3] - __bfloat162float(h3));
        *reinterpret_cast<__nv_bfloat162*>(&Oh[idx])     = hp0;
        *reinterpret_cast<__nv_bfloat162*>(&Oh[idx + 2]) = hp1;
        *reinterpret_cast<__nv_bfloat162*>(&Ol[idx])     = lp0;
        *reinterpret_cast<__nv_bfloat162*>(&Ol[idx + 2]) = lp1;
    }
}

// ---------------------------------------------------------------------------
// Fused residual + LayerNorm; optional bf16 split output (for x1 -> FFN A).
// ---------------------------------------------------------------------------
__global__ __launch_bounds__(256) void add_ln_kernel(
    const float* __restrict__ x, const float* __restrict__ r,
    const float* __restrict__ gamma, const float* __restrict__ beta,
    float* __restrict__ out,
    __nv_bfloat16* __restrict__ oh, __nv_bfloat16* __restrict__ ol)
{
    const int row = blockIdx.x;
    const int tid = threadIdx.x;
    const float* xr = x + (size_t)row * EMB;
    const float* rr = r + (size_t)row * EMB;

    float v[3];
    float s = 0.f;
#pragma unroll
    for (int i = 0; i < 3; i++) {
        int cx = tid + i * 256;
        float t = xr[cx] + rr[cx];
        v[i] = t;
        s += t;
    }

    __shared__ float red[8];
    const int wid = tid >> 5, lane = tid & 31;
#pragma unroll
    for (int o = 16; o > 0; o >>= 1) s += __shfl_xor_sync(0xffffffffu, s, o);
    if (lane == 0) red[wid] = s;
    __syncthreads();
    if (tid == 0) {
        float t = 0.f;
#pragma unroll
        for (int i = 0; i < 8; i++) t += red[i];
        red[0] = t;
    }
    __syncthreads();
    const float mean = red[0] * (1.0f / 768.0f);

    float s2 = 0.f;
#pragma unroll
    for (int i = 0; i < 3; i++) {
        float d = v[i] - mean;
        s2 += d * d;
    }
#pragma unroll
    for (int o = 16; o > 0; o >>= 1) s2 += __shfl_xor_sync(0xffffffffu, s2, o);
    __syncthreads();
    if (lane == 0) red[wid] = s2;
    __syncthreads();
    if (tid == 0) {
        float t = 0.f;
#pragma unroll
        for (int i = 0; i < 8; i++) t += red[i];
        red[0] = t;
    }
    __syncthreads();
    const float var  = red[0] * (1.0f / 768.0f);
    const float rstd = rsqrtf(var + 1e-5f);

#pragma unroll
    for (int i = 0; i < 3; i++) {
        int cx = tid + i * 256;
        float o = (v[i] - mean) * rstd * gamma[cx] + beta[cx];
        size_t idx = (size_t)row * EMB + cx;
        out[idx] = o;
        if (oh) {
            __nv_bfloat16 hh = __float2bfloat16(o);
            oh[idx] = hh;
            ol[idx] = __float2bfloat16(o - __bfloat162float(hh));
        }
    }
}

// ---------------------------------------------------------------------------
// Launch
// ---------------------------------------------------------------------------
extern "C" void kernel_launch(void* const* d_in, const int* in_sizes, int n_in,
                              void* d_out, int out_size)
{
    (void)in_sizes; (void)n_in; (void)out_size;

    const float* x   = (const float*)d_in[0];
    const float* Wq  = (const float*)d_in[1];
    const float* Wk  = (const float*)d_in[2];
    const float* Wv  = (const float*)d_in[3];
    const float* Wo  = (const float*)d_in[4];
    const float* W1  = (const float*)d_in[5];
    const float* b1  = (const float*)d_in[6];
    const float* W2  = (const float*)d_in[7];
    const float* b2  = (const float*)d_in[8];
    const float* g1  = (const float*)d_in[9];
    const float* be1 = (const float*)d_in[10];
    const float* g2  = (const float*)d_in[11];
    const float* be2 = (const float*)d_in[12];
    float* out = (float*)d_out;

    float *q, *k, *v, *tmp, *x1;
    __nv_bfloat16 *ah, *al, *ch, *cl, *fh, *fl, *wh, *wl;
    cudaGetSymbolAddress((void**)&q,   g_q);
    cudaGetSymbolAddress((void**)&k,   g_k);
    cudaGetSymbolAddress((void**)&v,   g_v);
    cudaGetSymbolAddress((void**)&tmp, g_tmp);
    cudaGetSymbolAddress((void**)&x1,  g_x1);
    cudaGetSymbolAddress((void**)&ah,  g_ah);
    cudaGetSymbolAddress((void**)&al,  g_al);
    cudaGetSymbolAddress((void**)&ch,  g_ch);
    cudaGetSymbolAddress((void**)&cl,  g_cl);
    cudaGetSymbolAddress((void**)&fh,  g_fh);
    cudaGetSymbolAddress((void**)&fl,  g_fl);
    cudaGetSymbolAddress((void**)&wh,  g_wh);
    cudaGetSymbolAddress((void**)&wl,  g_wl);

    const int ATTN_SMEM = (2048 + 4096 + 64 * 68 + 16384) * 4;
    cudaFuncSetAttribute(attn_kernel,
                         cudaFuncAttributeMaxDynamicSharedMemorySize, ATTN_SMEM);

    const size_t EE  = (size_t)EMB * EMB;        // 589824
    const size_t EF  = (size_t)EMB * FFND;       // 2359296
    const size_t OQ_ = 0, OK_ = EE, OV_ = 2 * EE, OO_ = 3 * EE;
    const size_t O1_ = 4 * EE, O2_ = 4 * EE + EF;

    dim3 blk(256);

    // splits: activations + weights
    split_kernel<<<NTOK * EMB / 1024, blk>>>(x, ah, al, NTOK * EMB);
    split_kernel<<<(int)(EE / 1024), blk>>>(Wq, wh + OQ_, wl + OQ_, (int)EE);
    split_kernel<<<(int)(EE / 1024), blk>>>(Wk, wh + OK_, wl + OK_, (int)EE);
    split_kernel<<<(int)(EE / 1024), blk>>>(Wv, wh + OV_, wl + OV_, (int)EE);
    split_kernel<<<(int)(EE / 1024), blk>>>(Wo, wh + OO_, wl + OO_, (int)EE);
    split_kernel<<<(int)(EF / 1024), blk>>>(W1, wh + O1_, wl + O1_, (int)EF);
    split_kernel<<<(int)(EF / 1024), blk>>>(W2, wh + O2_, wl + O2_, (int)EF);

    dim3 gE(EMB / 128,  NTOK / 128);
    dim3 gF(FFND / 128, NTOK / 128);

    // QKV projections
    tgemm<0><<<gE, blk>>>(ah, al, wh + OQ_, wl + OQ_, nullptr, q, nullptr, nullptr, NTOK, EMB, EMB);
    tgemm<0><<<gE, blk>>>(ah, al, wh + OK_, wl + OK_, nullptr, k, nullptr, nullptr, NTOK, EMB, EMB);
    tgemm<0><<<gE, blk>>>(ah, al, wh + OV_, wl + OV_, nullptr, v, nullptr, nullptr, NTOK, EMB, EMB);

    // attention -> ctx (bf16 split)
    attn_kernel<<<dim3(SEQ / 32, HEADS, BATCH), blk, ATTN_SMEM>>>(q, k, v, ch, cl);

    // output projection
    tgemm<0><<<gE, blk>>>(ch, cl, wh + OO_, wl + OO_, nullptr, tmp, nullptr, nullptr, NTOK, EMB, EMB);

    // residual + LN1 (also emits x1 as bf16 split into ah/al)
    add_ln_kernel<<<NTOK, blk>>>(x, tmp, g1, be1, x1, ah, al);

    // FFN1: bias+relu, bf16-split output only
    tgemm<3><<<gF, blk>>>(ah, al, wh + O1_, wl + O1_, b1, nullptr, fh, fl, NTOK, FFND, EMB);
    // FFN2: bias, fp32 output
    tgemm<1><<<gE, blk>>>(fh, fl, wh + O2_, wl + O2_, b2, tmp, nullptr, nullptr, NTOK, EMB, FFND);

    // residual + LN2
    add_ln_kernel<<<NTOK, blk>>>(x1, tmp, g2, be2, out, nullptr, nullptr);
}